// round 7
// baseline (speedup 1.0000x reference)
#include <cuda_runtime.h>
#include <cuda_fp16.h>
#include <stdint.h>

#define DD      256
#define NNODES  50000
#define NEDGES  300000
#define SCALE     64.0f
#define INV_SCALE 0.015625f

// Device scratch (no runtime allocation allowed)
__device__ float  g_proj[(size_t)NNODES * 512];   // scaled by 64: [n][0:256)=src, [256:512)=tgt
__device__ __half g_Wh[256 * 768];                // Wt[n][k] = fp16(64 * W[k][n])

// ---------------------------------------------------------------------------
__global__ void prep_w(const float* __restrict__ W) {
    const int k = blockIdx.x;      // 0..767
    const int n = threadIdx.x;     // 0..255
    g_Wh[(size_t)n * 768 + k] = __float2half_rn(SCALE * W[(size_t)k * DD + n]);
}

// ---------------------------------------------------------------------------
__device__ __forceinline__ uint32_t smem_u32(const void* p) {
    uint32_t a;
    asm("{ .reg .u64 t; cvta.to.shared.u64 t, %1; cvt.u32.u64 %0, t; }" : "=r"(a) : "l"(p));
    return a;
}
__device__ __forceinline__ void ldsm4(uint32_t* r, uint32_t a) {
    asm volatile("ldmatrix.sync.aligned.m8n8.x4.shared.b16 {%0,%1,%2,%3}, [%4];"
                 : "=r"(r[0]), "=r"(r[1]), "=r"(r[2]), "=r"(r[3]) : "r"(a));
}
__device__ __forceinline__ void mma16816(float* d, const uint32_t* a, const uint32_t* b) {
    asm volatile("mma.sync.aligned.m16n8k16.row.col.f32.f16.f16.f32 "
                 "{%0,%1,%2,%3}, {%4,%5,%6,%7}, {%8,%9}, {%0,%1,%2,%3};"
                 : "+f"(d[0]), "+f"(d[1]), "+f"(d[2]), "+f"(d[3])
                 : "r"(a[0]), "r"(a[1]), "r"(a[2]), "r"(a[3]), "r"(b[0]), "r"(b[1]));
}
__device__ __forceinline__ uint32_t cvt2h(float2 v) {
    __half2 h = __float22half2_rn(v);
    return *(uint32_t*)&h;
}

#define NTHR 512
#define BSTR 264                         // halfs per B smem row (+pad)
#define B_HALFS (256 * BSTR)             // 67584
#define SMEM_BYTES (B_HALFS * 2)         // 135168 B

// 512 threads, warp grid 4(m) x 4(n), warp tile 32 x 64. BM=128, BN=256.
// A fragments loaded DIRECTLY from global fp32 (no smem, no mainloop syncs).
// MODE 0: proj(scaled) = node @ [Wsrc|Wtgt]h, M=50000, N=512 (2 n-blocks of 256)
// MODE 1: out = relu((edge@W0h + proj[src] + proj[tgt]) * INV_SCALE + b), M=300000, N=256
template <int MODE>
__global__ __launch_bounds__(NTHR, 1)
void gemm_kernel(const float* __restrict__ Amat, const int* __restrict__ src,
                 const int* __restrict__ tgt, const float* __restrict__ bias,
                 float* __restrict__ out)
{
    constexpr int MTOT = (MODE == 0) ? NNODES : NEDGES;

    extern __shared__ __half Bs[];

    const int tid  = threadIdx.x;
    const int wid  = tid >> 5, lane = tid & 31;
    const int wm   = wid >> 2, wn = wid & 3;       // 4m x 4n; warp tile 32 x 64
    const int m0   = blockIdx.x * 128;
    const int nb   = blockIdx.y;
    const int koff = (MODE == 0) ? (256 + nb * 256) : 0;

    // ---- load resident B tile: 256 n-rows x 256 k halfs ----
    {
        const int r  = tid >> 1;
        const int kh = (tid & 1) * 128;
        const uint4* s4 = (const uint4*)(g_Wh + (size_t)r * 768 + koff + kh);
        uint4* d4 = (uint4*)(Bs + r * BSTR + kh);
        #pragma unroll
        for (int i = 0; i < 16; i++) d4[i] = s4[i];
    }
    __syncthreads();

    // ---- B ldmatrix base addresses ----
    uint32_t b_addr[4];
    {
        const int nrow = wn * 64 + (lane >> 4) * 8 + (lane & 7);
        const int kb   = ((lane >> 3) & 1) * 8;
        #pragma unroll
        for (int g = 0; g < 4; g++)
            b_addr[g] = smem_u32(Bs + (nrow + g * 16) * BSTR + kb);
    }

    // ---- A row pointers: 4 rows per lane (2 m-tiles x {g, g+8}) ----
    const int g = lane >> 2, q = lane & 3;
    const float* pA[4];
    bool val[4];
    #pragma unroll
    for (int i = 0; i < 2; i++)
        #pragma unroll
        for (int h = 0; h < 2; h++) {
            const int r = m0 + wm * 32 + i * 16 + h * 8 + g;
            val[i * 2 + h] = (r < MTOT);
            pA[i * 2 + h]  = Amat + (size_t)(val[i * 2 + h] ? r : 0) * DD + q * 2;
        }

    float acc[2][8][4];
    #pragma unroll
    for (int i = 0; i < 2; i++)
        #pragma unroll
        for (int j = 0; j < 8; j++)
            #pragma unroll
            for (int qq = 0; qq < 4; qq++) acc[i][j][qq] = 0.f;

    auto ldA = [&](int ks, float2* raw) {
        #pragma unroll
        for (int j = 0; j < 4; j++)
            #pragma unroll
            for (int kb = 0; kb < 2; kb++)
                raw[j * 2 + kb] = val[j] ? *(const float2*)(pA[j] + ks * 16 + kb * 8)
                                         : make_float2(0.f, 0.f);
    };

    // ---- mainloop: 16 k-steps, zero syncs, depth-1 A prefetch ----
    float2 raw0[8], raw1[8];
    ldA(0, raw0);
    #pragma unroll
    for (int ks = 0; ks < 16; ks++) {
        float2* cur = (ks & 1) ? raw1 : raw0;
        float2* nxt = (ks & 1) ? raw0 : raw1;
        if (ks < 15) ldA(ks + 1, nxt);

        // convert A fragments: a[i] = {(r,k0),(r+8,k0),(r,k8),(r+8,k8)}
        uint32_t ah[2][4];
        #pragma unroll
        for (int i = 0; i < 2; i++) {
            ah[i][0] = cvt2h(cur[i * 4 + 0]);
            ah[i][1] = cvt2h(cur[i * 4 + 2]);
            ah[i][2] = cvt2h(cur[i * 4 + 1]);
            ah[i][3] = cvt2h(cur[i * 4 + 3]);
        }

        const uint32_t boff = (uint32_t)(ks * 32);   // 16 halfs = 32 bytes
        #pragma unroll
        for (int gg = 0; gg < 4; gg++) {
            uint32_t bf[4];
            ldsm4(bf, b_addr[gg] + boff);
            mma16816(acc[0][2 * gg],     ah[0], &bf[0]);
            mma16816(acc[0][2 * gg + 1], ah[0], &bf[2]);
            mma16816(acc[1][2 * gg],     ah[1], &bf[0]);
            mma16816(acc[1][2 * gg + 1], ah[1], &bf[2]);
        }
    }

    // ---- epilogue (warp covers cols wn*64 .. wn*64+63) ----
    const int grp = lane >> 2, qc = (lane & 3) * 2;
    const int colw = wn * 64;
    #pragma unroll
    for (int i = 0; i < 2; i++) {
        #pragma unroll
        for (int h = 0; h < 2; h++) {
            const int gm = m0 + wm * 32 + i * 16 + grp + h * 8;
            if (gm >= MTOT) continue;
            if (MODE == 0) {
                float* pp = g_proj + (size_t)gm * 512 + nb * 256 + colw;
                #pragma unroll
                for (int j = 0; j < 8; j++)
                    *(float2*)(pp + j * 8 + qc) =
                        make_float2(acc[i][j][2 * h], acc[i][j][2 * h + 1]);
            } else {
                const int si = src[gm], ti = tgt[gm];
                const float* ps = g_proj + (size_t)si * 512 + colw;
                const float* pt = g_proj + (size_t)ti * 512 + 256 + colw;
                const float* bb = bias + colw;
                float* op = out + (size_t)gm * DD + colw;
                #pragma unroll
                for (int j = 0; j < 8; j++) {
                    const int cc = j * 8 + qc;
                    float2 sv = *(const float2*)(ps + cc);
                    float2 tv = *(const float2*)(pt + cc);
                    float2 bv = *(const float2*)(bb + cc);
                    float x = fmaf(acc[i][j][2 * h]     + sv.x + tv.x, INV_SCALE, bv.x);
                    float y = fmaf(acc[i][j][2 * h + 1] + sv.y + tv.y, INV_SCALE, bv.y);
                    *(float2*)(op + cc) = make_float2(fmaxf(x, 0.f), fmaxf(y, 0.f));
                }
            }
        }
    }
}

// ---------------------------------------------------------------------------
extern "C" void kernel_launch(void* const* d_in, const int* in_sizes, int n_in,
                              void* d_out, int out_size)
{
    const float* edge_feat = (const float*)d_in[0];
    const float* node_feat = (const float*)d_in[1];
    const int*   src_idx   = (const int*)d_in[2];
    const int*   tgt_idx   = (const int*)d_in[3];
    const float* W         = (const float*)d_in[4];
    const float* b         = (const float*)d_in[5];
    float* out = (float*)d_out;
    (void)in_sizes; (void)n_in; (void)out_size;

    cudaFuncSetAttribute(gemm_kernel<0>, cudaFuncAttributeMaxDynamicSharedMemorySize, SMEM_BYTES);
    cudaFuncSetAttribute(gemm_kernel<1>, cudaFuncAttributeMaxDynamicSharedMemorySize, SMEM_BYTES);

    prep_w<<<768, 256>>>(W);
    gemm_kernel<0><<<dim3(391, 2),  NTHR, SMEM_BYTES>>>(node_feat, nullptr, nullptr, nullptr, nullptr);
    gemm_kernel<1><<<dim3(2344, 1), NTHR, SMEM_BYTES>>>(edge_feat, src_idx, tgt_idx, b, out);
}

// round 8
// speedup vs baseline: 1.0727x; 1.0727x over previous
#include <cuda_runtime.h>
#include <cuda_fp16.h>
#include <stdint.h>

#define DD      256
#define NNODES  50000
#define NEDGES  300000
#define SCALE     64.0f
#define INV_SCALE 0.015625f

// Device scratch (no runtime allocation allowed)
__device__ float  g_proj[(size_t)NNODES * 512];   // scaled by 64: [n][0:256)=src, [256:512)=tgt
__device__ __half g_Wh[256 * 768];                // Wt[n][k] = fp16(64 * W[k][n])

// ---------------------------------------------------------------------------
__global__ void prep_w(const float* __restrict__ W) {
    const int k = blockIdx.x;      // 0..767
    const int n = threadIdx.x;     // 0..255
    g_Wh[(size_t)n * 768 + k] = __float2half_rn(SCALE * W[(size_t)k * DD + n]);
}

// ---------------------------------------------------------------------------
__device__ __forceinline__ uint32_t smem_u32(const void* p) {
    uint32_t a;
    asm("{ .reg .u64 t; cvta.to.shared.u64 t, %1; cvt.u32.u64 %0, t; }" : "=r"(a) : "l"(p));
    return a;
}
__device__ __forceinline__ void ldsm4(uint32_t* r, uint32_t a) {
    asm volatile("ldmatrix.sync.aligned.m8n8.x4.shared.b16 {%0,%1,%2,%3}, [%4];"
                 : "=r"(r[0]), "=r"(r[1]), "=r"(r[2]), "=r"(r[3]) : "r"(a));
}
__device__ __forceinline__ void mma16816(float* d, const uint32_t* a, const uint32_t* b) {
    asm volatile("mma.sync.aligned.m16n8k16.row.col.f32.f16.f16.f32 "
                 "{%0,%1,%2,%3}, {%4,%5,%6,%7}, {%8,%9}, {%0,%1,%2,%3};"
                 : "+f"(d[0]), "+f"(d[1]), "+f"(d[2]), "+f"(d[3])
                 : "r"(a[0]), "r"(a[1]), "r"(a[2]), "r"(a[3]), "r"(b[0]), "r"(b[1]));
}

#define NTHR 256
#define BSTR 264                                   // halfs per B smem row (+pad)
#define ASTR 40                                    // halfs per A smem row
#define B_HALFS (128 * BSTR)                       // 33792
#define A_HALFS (128 * ASTR)                       // 5120
#define SMEM_BYTES ((B_HALFS + 3 * A_HALFS) * 2)   // 98304 B -> 2 CTAs/SM

// 256 threads, warp grid 4(m) x 2(n), warp tile 32 x 64. BM=128, BN=128.
// 3-stage A ring, one __syncthreads per K-chunk. Two CTAs co-resident per SM
// so one CTA's mainloop covers the other's prologue/epilogue pipe bubbles.
// MODE 0: proj(scaled) = node @ [Wsrc|Wtgt]h, M=50000, N=512 (4 n-blocks of 128)
// MODE 1: out = relu((edge@W0h + proj[src] + proj[tgt]) * INV_SCALE + b), N=256 (2 n-blocks)
template <int MODE>
__global__ __launch_bounds__(NTHR, 2)
void gemm_kernel(const float* __restrict__ Amat, const int* __restrict__ src,
                 const int* __restrict__ tgt, const float* __restrict__ bias,
                 float* __restrict__ out)
{
    constexpr int MTOT = (MODE == 0) ? NNODES : NEDGES;

    extern __shared__ __half sh[];
    __half* Bs = sh;
    auto As = [&](int buf) { return sh + B_HALFS + buf * A_HALFS; };

    const int tid  = threadIdx.x;
    const int wid  = tid >> 5, lane = tid & 31;
    const int wm   = wid >> 1, wn = wid & 1;       // 4m x 2n; warp tile 32 x 64
    const int m0   = blockIdx.x * 128;
    const int nb   = blockIdx.y;
    const int rowb = (MODE == 0) ? ((nb & 1) * 128) : (nb * 128);
    const int koff = (MODE == 0) ? (256 + (nb >> 1) * 256) : 0;
    const int dcol = (MODE == 0) ? ((nb >> 1) * 256 + (nb & 1) * 128) : (nb * 128);

    // ---- load resident B tile: 128 n-rows x 256 k halfs ----
    {
        const int r  = tid >> 1;
        const int kh = (tid & 1) * 128;
        const uint4* s4 = (const uint4*)(g_Wh + (size_t)(rowb + r) * 768 + koff + kh);
        uint4* d4 = (uint4*)(Bs + r * BSTR + kh);
        #pragma unroll
        for (int i = 0; i < 16; i++) d4[i] = s4[i];
    }

    // ---- A streaming (chunk = 128 rows x 32 k floats; 16 floats/thread) ----
    const int ar  = tid >> 1;
    const int akq = (tid & 1) * 16;
    float4 pre[4];
    auto ldgA = [&](int c) {
        const int gm = m0 + ar;
        if (gm < MTOT) {
            const float4* p = (const float4*)(Amat + (size_t)gm * DD + c * 32 + akq);
            pre[0] = p[0]; pre[1] = p[1]; pre[2] = p[2]; pre[3] = p[3];
        } else {
            pre[0] = pre[1] = pre[2] = pre[3] = make_float4(0.f, 0.f, 0.f, 0.f);
        }
    };
    auto stsA = [&](int buf) {
        const float* f = (const float*)pre;
        uint32_t hu[8];
        #pragma unroll
        for (int q = 0; q < 8; q++) {
            __half h0 = __float2half_rn(f[2 * q]);
            __half h1 = __float2half_rn(f[2 * q + 1]);
            hu[q] = ((uint32_t)__half_as_ushort(h1) << 16) | __half_as_ushort(h0);
        }
        uint4* dh = (uint4*)(As(buf) + ar * ASTR + akq);
        dh[0] = make_uint4(hu[0], hu[1], hu[2], hu[3]);
        dh[1] = make_uint4(hu[4], hu[5], hu[6], hu[7]);
    };

    // ---- ldmatrix base addresses ----
    uint32_t b_addr[4];
    {
        const int nrow = wn * 64 + (lane >> 4) * 8 + (lane & 7);
        const int kb   = ((lane >> 3) & 1) * 8;
        #pragma unroll
        for (int g = 0; g < 4; g++)
            b_addr[g] = smem_u32(Bs + (nrow + g * 16) * BSTR + kb);
    }
    uint32_t a_base;
    {
        const int arow = wm * 32 + (lane & 15);
        const int acb  = (lane >> 4) * 8;
        a_base = smem_u32(As(0) + arow * ASTR + acb);
    }

    float acc[2][8][4];
    #pragma unroll
    for (int i = 0; i < 2; i++)
        #pragma unroll
        for (int j = 0; j < 8; j++)
            #pragma unroll
            for (int q = 0; q < 4; q++) acc[i][j][q] = 0.f;

    // ---- prologue: fill stage 0, prefetch stage 1 ----
    ldgA(0); stsA(0); ldgA(1);
    __syncthreads();

    // ---- mainloop: ONE sync per chunk (3-stage ring) ----
    #pragma unroll 1
    for (int c = 0; c < 8; c++) {
        if (c < 7) stsA((c + 1) % 3);
        if (c < 6) ldgA(c + 2);

        const uint32_t abuf = a_base + (uint32_t)((c % 3) * A_HALFS * 2);
        const uint32_t boff = (uint32_t)(c * 64);   // bytes

        #pragma unroll
        for (int s = 0; s < 2; s++) {
            uint32_t ah[2][4], bf[4][4];
            ldsm4(ah[0], abuf + s * 32);
            ldsm4(ah[1], abuf + 16 * ASTR * 2 + s * 32);
            #pragma unroll
            for (int g = 0; g < 4; g++) ldsm4(bf[g], b_addr[g] + boff + s * 32);

            #pragma unroll
            for (int g = 0; g < 4; g++) {
                mma16816(acc[0][2 * g],     ah[0], &bf[g][0]);
                mma16816(acc[0][2 * g + 1], ah[0], &bf[g][2]);
                mma16816(acc[1][2 * g],     ah[1], &bf[g][0]);
                mma16816(acc[1][2 * g + 1], ah[1], &bf[g][2]);
            }
        }
        __syncthreads();
    }

    // ---- epilogue (warp covers cols dcol + wn*64 ..+63) ----
    const int grp = lane >> 2, qc = (lane & 3) * 2;
    const int colw = wn * 64;
    #pragma unroll
    for (int i = 0; i < 2; i++) {
        #pragma unroll
        for (int h = 0; h < 2; h++) {
            const int gm = m0 + wm * 32 + i * 16 + grp + h * 8;
            if (gm >= MTOT) continue;
            if (MODE == 0) {
                float* pp = g_proj + (size_t)gm * 512 + dcol + colw;
                #pragma unroll
                for (int j = 0; j < 8; j++)
                    *(float2*)(pp + j * 8 + qc) =
                        make_float2(acc[i][j][2 * h], acc[i][j][2 * h + 1]);
            } else {
                const int si = src[gm], ti = tgt[gm];
                const float* ps = g_proj + (size_t)si * 512 + dcol + colw;
                const float* pt = g_proj + (size_t)ti * 512 + 256 + dcol + colw;
                const float* bb = bias + dcol + colw;
                float* op = out + (size_t)gm * DD + dcol + colw;
                #pragma unroll
                for (int j = 0; j < 8; j++) {
                    const int cc = j * 8 + qc;
                    float2 sv = *(const float2*)(ps + cc);
                    float2 tv = *(const float2*)(pt + cc);
                    float2 bv = *(const float2*)(bb + cc);
                    float x = fmaf(acc[i][j][2 * h]     + sv.x + tv.x, INV_SCALE, bv.x);
                    float y = fmaf(acc[i][j][2 * h + 1] + sv.y + tv.y, INV_SCALE, bv.y);
                    *(float2*)(op + cc) = make_float2(fmaxf(x, 0.f), fmaxf(y, 0.f));
                }
            }
        }
    }
}

// ---------------------------------------------------------------------------
extern "C" void kernel_launch(void* const* d_in, const int* in_sizes, int n_in,
                              void* d_out, int out_size)
{
    const float* edge_feat = (const float*)d_in[0];
    const float* node_feat = (const float*)d_in[1];
    const int*   src_idx   = (const int*)d_in[2];
    const int*   tgt_idx   = (const int*)d_in[3];
    const float* W         = (const float*)d_in[4];
    const float* b         = (const float*)d_in[5];
    float* out = (float*)d_out;
    (void)in_sizes; (void)n_in; (void)out_size;

    cudaFuncSetAttribute(gemm_kernel<0>, cudaFuncAttributeMaxDynamicSharedMemorySize, SMEM_BYTES);
    cudaFuncSetAttribute(gemm_kernel<1>, cudaFuncAttributeMaxDynamicSharedMemorySize, SMEM_BYTES);

    prep_w<<<768, 256>>>(W);
    gemm_kernel<0><<<dim3(391, 4),  NTHR, SMEM_BYTES>>>(node_feat, nullptr, nullptr, nullptr, nullptr);
    gemm_kernel<1><<<dim3(2344, 2), NTHR, SMEM_BYTES>>>(edge_feat, src_idx, tgt_idx, b, out);
}

// round 9
// speedup vs baseline: 1.3862x; 1.2922x over previous
#include <cuda_runtime.h>
#include <cuda_fp16.h>
#include <stdint.h>

#define DD      256
#define NNODES  50000
#define NEDGES  300000
#define SCALE     64.0f
#define INV_SCALE 0.015625f
#define GRID    148
#define NTHR    512

// Device scratch (no runtime allocation allowed)
__device__ float  g_proj[(size_t)NNODES * 512];   // scaled by 64: [n][0:256)=src, [256:512)=tgt
__device__ __half g_Wh[256 * 768];                // Wt[n][k] = fp16(64 * W[k][n])

// ---------------------------------------------------------------------------
__global__ void prep_w(const float* __restrict__ W) {
    const int k = blockIdx.x;      // 0..767
    const int n = threadIdx.x;     // 0..255
    g_Wh[(size_t)n * 768 + k] = __float2half_rn(SCALE * W[(size_t)k * DD + n]);
}

// ---------------------------------------------------------------------------
__device__ __forceinline__ uint32_t smem_u32(const void* p) {
    uint32_t a;
    asm("{ .reg .u64 t; cvta.to.shared.u64 t, %1; cvt.u32.u64 %0, t; }" : "=r"(a) : "l"(p));
    return a;
}
__device__ __forceinline__ void ldsm4(uint32_t* r, uint32_t a) {
    asm volatile("ldmatrix.sync.aligned.m8n8.x4.shared.b16 {%0,%1,%2,%3}, [%4];"
                 : "=r"(r[0]), "=r"(r[1]), "=r"(r[2]), "=r"(r[3]) : "r"(a));
}
__device__ __forceinline__ void mma16816(float* d, const uint32_t* a, const uint32_t* b) {
    asm volatile("mma.sync.aligned.m16n8k16.row.col.f32.f16.f16.f32 "
                 "{%0,%1,%2,%3}, {%4,%5,%6,%7}, {%8,%9}, {%0,%1,%2,%3};"
                 : "+f"(d[0]), "+f"(d[1]), "+f"(d[2]), "+f"(d[3])
                 : "r"(a[0]), "r"(a[1]), "r"(a[2]), "r"(a[3]), "r"(b[0]), "r"(b[1]));
}

#define BSTR 264                                   // halfs per B smem row (+pad)
#define ASTR 40                                    // halfs per A smem row
#define B_HALFS (256 * BSTR)                       // 67584
#define A_HALFS (128 * ASTR)                       // 5120
#define SMEM_BYTES ((B_HALFS + 3 * A_HALFS) * 2)   // 165888 B

// Persistent: grid=148, one CTA/SM. B tile (256 x 256 halfs) loaded ONCE per
// n-block; A chunk pipeline (3-stage ring, one sync per chunk) runs
// continuously across tile boundaries so the epilogue overlaps the next
// tile's A prefetch. Warp grid 4(m) x 4(n), warp tile 32 x 64.
// MODE 0: proj(scaled) = node @ [Wsrc|Wtgt]h, M=50000, N=512 (2 n-blocks)
// MODE 1: out = relu((edge@W0h + proj[src] + proj[tgt]) * INV_SCALE + b), N=256
template <int MODE>
__global__ __launch_bounds__(NTHR, 1)
void gemm_kernel(const float* __restrict__ Amat, const int* __restrict__ src,
                 const int* __restrict__ tgt, const float* __restrict__ bias,
                 float* __restrict__ out)
{
    constexpr int MTOT   = (MODE == 0) ? NNODES : NEDGES;
    constexpr int MT     = (MTOT + 127) / 128;
    constexpr int NBLK   = (MODE == 0) ? 2 : 1;
    constexpr int NTILES = MT * NBLK;

    extern __shared__ __half sh[];
    __half* Bs = sh;
    auto As = [&](int buf) { return sh + B_HALFS + buf * A_HALFS; };

    const int tid  = threadIdx.x;
    const int wid  = tid >> 5, lane = tid & 31;
    const int wm   = wid >> 2, wn = wid & 3;        // 4m x 4n; warp tile 32 x 64
    const int bid  = blockIdx.x;

    const int nt = (NTILES - bid + GRID - 1) / GRID;   // tiles for this CTA
    if (nt <= 0) return;
    const int total_chunks = nt * 8;

    // ---- resident B tile loader (256 n-rows x 256 k halfs) ----
    auto loadB = [&](int nb) {
        const int koff = (MODE == 0) ? (256 + nb * 256) : 0;
        const int r  = tid >> 1;
        const int kh = (tid & 1) * 128;
        const uint4* s4 = (const uint4*)(g_Wh + (size_t)r * 768 + koff + kh);
        uint4* d4 = (uint4*)(Bs + r * BSTR + kh);
        #pragma unroll
        for (int i = 0; i < 16; i++) d4[i] = s4[i];
    };

    // ---- A streaming (chunk = 128 rows x 32 k floats; 8 floats/thread) ----
    const int ar  = tid >> 2;
    const int akq = (tid & 3) * 8;
    float4 pre[2];
    auto ldgA = [&](int g) {                       // g = global chunk id for this CTA
        const int ti = g >> 3;
        const int t  = bid + ti * GRID;
        const int m0 = (t % MT) * 128;
        const int c  = g & 7;
        const int gm = m0 + ar;
        if (gm < MTOT) {
            const float4* p = (const float4*)(Amat + (size_t)gm * DD + c * 32 + akq);
            pre[0] = p[0]; pre[1] = p[1];
        } else {
            pre[0] = pre[1] = make_float4(0.f, 0.f, 0.f, 0.f);
        }
    };
    auto stsA = [&](int buf) {
        const float* f = (const float*)pre;
        uint32_t hu[4];
        #pragma unroll
        for (int q = 0; q < 4; q++) {
            __half h0 = __float2half_rn(f[2 * q]);
            __half h1 = __float2half_rn(f[2 * q + 1]);
            hu[q] = ((uint32_t)__half_as_ushort(h1) << 16) | __half_as_ushort(h0);
        }
        *(uint4*)(As(buf) + ar * ASTR + akq) = make_uint4(hu[0], hu[1], hu[2], hu[3]);
    };

    // ---- ldmatrix base addresses (fixed for all tiles) ----
    uint32_t b_addr[4];
    {
        const int nrow = wn * 64 + (lane >> 4) * 8 + (lane & 7);
        const int kb   = ((lane >> 3) & 1) * 8;
        #pragma unroll
        for (int g = 0; g < 4; g++)
            b_addr[g] = smem_u32(Bs + (nrow + g * 16) * BSTR + kb);
    }
    uint32_t a_base;
    {
        const int arow = wm * 32 + (lane & 15);
        const int acb  = (lane >> 4) * 8;
        a_base = smem_u32(As(0) + arow * ASTR + acb);
    }

    // ---- first tile prologue ----
    int cur_nb = (MODE == 0) ? (bid / MT) : 0;
    loadB(cur_nb);
    ldgA(0); stsA(0);
    if (total_chunks > 1) ldgA(1);
    __syncthreads();

    const int grp = lane >> 2, qc = (lane & 3) * 2;
    const int colw = wn * 64;
    int g = 0;

    #pragma unroll 1
    for (int i = 0; i < nt; i++) {
        const int t  = bid + i * GRID;
        const int nb = (MODE == 0) ? (t / MT) : 0;
        const int m0 = (t % MT) * 128;

        if (nb != cur_nb) {            // at most once per CTA (mode 0 only)
            __syncthreads();
            loadB(nb);
            cur_nb = nb;
            __syncthreads();
        }

        float acc[2][8][4];
        #pragma unroll
        for (int ii = 0; ii < 2; ii++)
            #pragma unroll
            for (int j = 0; j < 8; j++)
                #pragma unroll
                for (int q = 0; q < 4; q++) acc[ii][j][q] = 0.f;

        // ---- mainloop: 8 chunks, one sync per chunk, pipeline spans tiles ----
        #pragma unroll 1
        for (int c = 0; c < 8; c++, g++) {
            if (g + 1 < total_chunks) stsA((g + 1) % 3);
            if (g + 2 < total_chunks) ldgA(g + 2);

            const uint32_t abuf = a_base + (uint32_t)((g % 3) * A_HALFS * 2);
            const uint32_t boff = (uint32_t)(c * 64);   // bytes

            #pragma unroll
            for (int s = 0; s < 2; s++) {
                uint32_t ah[2][4], bf[4][4];
                ldsm4(ah[0], abuf + s * 32);
                ldsm4(ah[1], abuf + 16 * ASTR * 2 + s * 32);
                #pragma unroll
                for (int gg = 0; gg < 4; gg++) ldsm4(bf[gg], b_addr[gg] + boff + s * 32);

                #pragma unroll
                for (int gg = 0; gg < 4; gg++) {
                    mma16816(acc[0][2 * gg],     ah[0], &bf[gg][0]);
                    mma16816(acc[0][2 * gg + 1], ah[0], &bf[gg][2]);
                    mma16816(acc[1][2 * gg],     ah[1], &bf[gg][0]);
                    mma16816(acc[1][2 * gg + 1], ah[1], &bf[gg][2]);
                }
            }
            __syncthreads();
        }

        // ---- epilogue (overlaps next tile's A prefetch already in flight) ----
        #pragma unroll
        for (int ii = 0; ii < 2; ii++) {
            #pragma unroll
            for (int h = 0; h < 2; h++) {
                const int gm = m0 + wm * 32 + ii * 16 + grp + h * 8;
                if (gm >= MTOT) continue;
                if (MODE == 0) {
                    float* pp = g_proj + (size_t)gm * 512 + nb * 256 + colw;
                    #pragma unroll
                    for (int j = 0; j < 8; j++)
                        *(float2*)(pp + j * 8 + qc) =
                            make_float2(acc[ii][j][2 * h], acc[ii][j][2 * h + 1]);
                } else {
                    const int si = src[gm], ti2 = tgt[gm];
                    const float* ps = g_proj + (size_t)si * 512 + colw;
                    const float* pt = g_proj + (size_t)ti2 * 512 + 256 + colw;
                    const float* bb = bias + colw;
                    float* op = out + (size_t)gm * DD + colw;
                    #pragma unroll
                    for (int j = 0; j < 8; j++) {
                        const int cc = j * 8 + qc;
                        float2 sv = *(const float2*)(ps + cc);
                        float2 tv = *(const float2*)(pt + cc);
                        float2 bv = *(const float2*)(bb + cc);
                        float x = fmaf(acc[ii][j][2 * h]     + sv.x + tv.x, INV_SCALE, bv.x);
                        float y = fmaf(acc[ii][j][2 * h + 1] + sv.y + tv.y, INV_SCALE, bv.y);
                        *(float2*)(op + cc) = make_float2(fmaxf(x, 0.f), fmaxf(y, 0.f));
                    }
                }
            }
        }
    }
}

// ---------------------------------------------------------------------------
extern "C" void kernel_launch(void* const* d_in, const int* in_sizes, int n_in,
                              void* d_out, int out_size)
{
    const float* edge_feat = (const float*)d_in[0];
    const float* node_feat = (const float*)d_in[1];
    const int*   src_idx   = (const int*)d_in[2];
    const int*   tgt_idx   = (const int*)d_in[3];
    const float* W         = (const float*)d_in[4];
    const float* b         = (const float*)d_in[5];
    float* out = (float*)d_out;
    (void)in_sizes; (void)n_in; (void)out_size;

    cudaFuncSetAttribute(gemm_kernel<0>, cudaFuncAttributeMaxDynamicSharedMemorySize, SMEM_BYTES);
    cudaFuncSetAttribute(gemm_kernel<1>, cudaFuncAttributeMaxDynamicSharedMemorySize, SMEM_BYTES);

    prep_w<<<768, 256>>>(W);
    gemm_kernel<0><<<GRID, NTHR, SMEM_BYTES>>>(node_feat, nullptr, nullptr, nullptr, nullptr);
    gemm_kernel<1><<<GRID, NTHR, SMEM_BYTES>>>(edge_feat, src_idx, tgt_idx, b, out);
}

// round 10
// speedup vs baseline: 1.5981x; 1.1528x over previous
#include <cuda_runtime.h>
#include <cuda_fp16.h>
#include <stdint.h>

#define DD      256
#define NNODES  50000
#define NEDGES  300000
#define SCALE     64.0f
#define INV_SCALE 0.015625f
#define GRID    148
#define NTHR    512

// Device scratch (no runtime allocation allowed)
__device__ __half g_proj[(size_t)NNODES * 512];   // fp16, scaled by 64: [n][0:256)=src, [256:512)=tgt
__device__ __half g_Wh[256 * 768];                // Wt[n][k] = fp16(64 * W[k][n])

// ---------------------------------------------------------------------------
__global__ void prep_w(const float* __restrict__ W) {
    const int k = blockIdx.x;      // 0..767
    const int n = threadIdx.x;     // 0..255
    g_Wh[(size_t)n * 768 + k] = __float2half_rn(SCALE * W[(size_t)k * DD + n]);
}

// ---------------------------------------------------------------------------
__device__ __forceinline__ uint32_t smem_u32(const void* p) {
    uint32_t a;
    asm("{ .reg .u64 t; cvta.to.shared.u64 t, %1; cvt.u32.u64 %0, t; }" : "=r"(a) : "l"(p));
    return a;
}
__device__ __forceinline__ void ldsm4(uint32_t* r, uint32_t a) {
    asm volatile("ldmatrix.sync.aligned.m8n8.x4.shared.b16 {%0,%1,%2,%3}, [%4];"
                 : "=r"(r[0]), "=r"(r[1]), "=r"(r[2]), "=r"(r[3]) : "r"(a));
}
__device__ __forceinline__ void mma16816(float* d, const uint32_t* a, const uint32_t* b) {
    asm volatile("mma.sync.aligned.m16n8k16.row.col.f32.f16.f16.f32 "
                 "{%0,%1,%2,%3}, {%4,%5,%6,%7}, {%8,%9}, {%0,%1,%2,%3};"
                 : "+f"(d[0]), "+f"(d[1]), "+f"(d[2]), "+f"(d[3])
                 : "r"(a[0]), "r"(a[1]), "r"(a[2]), "r"(a[3]), "r"(b[0]), "r"(b[1]));
}

#define BSTR 264                                   // halfs per B smem row (+pad)
#define ASTR 72                                    // halfs per A smem row (64 + 8 pad)
#define B_HALFS (256 * BSTR)                       // 67584
#define A_HALFS (128 * ASTR)                       // 9216
#define SMEM_BYTES ((B_HALFS + 3 * A_HALFS) * 2)   // 190464 B

// Persistent: grid=148. B (256x256 halfs) loaded once per n-block; A streamed
// in K=64 chunks (3-stage ring, ONE sync per chunk -> 4 syncs/tile), pipeline
// spans tile boundaries. Warp grid 4m x 4n, warp tile 32 x 64. proj in fp16.
// MODE 0: proj(scaled fp16) = node @ [Wsrc|Wtgt]h, M=50000, N=512 (2 n-blocks)
// MODE 1: out = relu((edge@W0h + proj[src] + proj[tgt]) * INV_SCALE + b), N=256
template <int MODE>
__global__ __launch_bounds__(NTHR, 1)
void gemm_kernel(const float* __restrict__ Amat, const int* __restrict__ src,
                 const int* __restrict__ tgt, const float* __restrict__ bias,
                 float* __restrict__ out)
{
    constexpr int MTOT   = (MODE == 0) ? NNODES : NEDGES;
    constexpr int MT     = (MTOT + 127) / 128;
    constexpr int NBLK   = (MODE == 0) ? 2 : 1;
    constexpr int NTILES = MT * NBLK;

    extern __shared__ __half sh[];
    __half* Bs = sh;
    auto As = [&](int buf) { return sh + B_HALFS + buf * A_HALFS; };

    const int tid  = threadIdx.x;
    const int wid  = tid >> 5, lane = tid & 31;
    const int wm   = wid >> 2, wn = wid & 3;        // 4m x 4n; warp tile 32 x 64
    const int bid  = blockIdx.x;

    const int nt = (NTILES - bid + GRID - 1) / GRID;
    if (nt <= 0) return;
    const int total_chunks = nt * 4;                // 4 chunks of K=64 per tile

    // ---- resident B tile loader ----
    auto loadB = [&](int nb) {
        const int koff = (MODE == 0) ? (256 + nb * 256) : 0;
        const int r  = tid >> 1;
        const int kh = (tid & 1) * 128;
        const uint4* s4 = (const uint4*)(g_Wh + (size_t)r * 768 + koff + kh);
        uint4* d4 = (uint4*)(Bs + r * BSTR + kh);
        #pragma unroll
        for (int i = 0; i < 16; i++) d4[i] = s4[i];
    };

    // ---- A streaming (chunk = 128 rows x 64 k floats; 16 floats/thread) ----
    const int ar  = tid >> 2;
    const int akq = (tid & 3) * 16;
    float4 pre[4];
    auto ldgA = [&](int g) {                        // g = global chunk id
        const int ti = g >> 2;
        const int t  = bid + ti * GRID;
        const int m0 = (t % MT) * 128;
        const int c  = g & 3;
        const int gm = m0 + ar;
        if (gm < MTOT) {
            const float4* p = (const float4*)(Amat + (size_t)gm * DD + c * 64 + akq);
            pre[0] = p[0]; pre[1] = p[1]; pre[2] = p[2]; pre[3] = p[3];
        } else {
            pre[0] = pre[1] = pre[2] = pre[3] = make_float4(0.f, 0.f, 0.f, 0.f);
        }
    };
    auto stsA = [&](int buf) {
        const float* f = (const float*)pre;
        uint32_t hu[8];
        #pragma unroll
        for (int q = 0; q < 8; q++) {
            __half h0 = __float2half_rn(f[2 * q]);
            __half h1 = __float2half_rn(f[2 * q + 1]);
            hu[q] = ((uint32_t)__half_as_ushort(h1) << 16) | __half_as_ushort(h0);
        }
        uint4* dh = (uint4*)(As(buf) + ar * ASTR + akq);
        dh[0] = make_uint4(hu[0], hu[1], hu[2], hu[3]);
        dh[1] = make_uint4(hu[4], hu[5], hu[6], hu[7]);
    };

    // ---- ldmatrix base addresses ----
    uint32_t b_addr[4];
    {
        const int nrow = wn * 64 + (lane >> 4) * 8 + (lane & 7);
        const int kb   = ((lane >> 3) & 1) * 8;
        #pragma unroll
        for (int g = 0; g < 4; g++)
            b_addr[g] = smem_u32(Bs + (nrow + g * 16) * BSTR + kb);
    }
    uint32_t a_base;
    {
        const int arow = wm * 32 + (lane & 15);
        const int acb  = (lane >> 4) * 8;
        a_base = smem_u32(As(0) + arow * ASTR + acb);
    }

    // ---- first tile prologue ----
    int cur_nb = (MODE == 0) ? (bid / MT) : 0;
    loadB(cur_nb);
    ldgA(0); stsA(0);
    if (total_chunks > 1) ldgA(1);
    __syncthreads();

    const int grp = lane >> 2, qc = (lane & 3) * 2;
    const int colw = wn * 64;
    int g = 0;

    #pragma unroll 1
    for (int i = 0; i < nt; i++) {
        const int t  = bid + i * GRID;
        const int nb = (MODE == 0) ? (t / MT) : 0;
        const int m0 = (t % MT) * 128;

        if (nb != cur_nb) {            // at most once per CTA (mode 0 only)
            __syncthreads();
            loadB(nb);
            cur_nb = nb;
            __syncthreads();
        }

        float acc[2][8][4];
        #pragma unroll
        for (int ii = 0; ii < 2; ii++)
            #pragma unroll
            for (int j = 0; j < 8; j++)
                #pragma unroll
                for (int q = 0; q < 4; q++) acc[ii][j][q] = 0.f;

        // ---- mainloop: 4 chunks of K=64, one sync per chunk ----
        #pragma unroll 1
        for (int c = 0; c < 4; c++, g++) {
            if (g + 1 < total_chunks) stsA((g + 1) % 3);
            if (g + 2 < total_chunks) ldgA(g + 2);

            const uint32_t abuf = a_base + (uint32_t)((g % 3) * A_HALFS * 2);
            const uint32_t boff = (uint32_t)(c * 128);   // bytes: 64 halfs/chunk

            #pragma unroll
            for (int s = 0; s < 4; s++) {
                uint32_t ah[2][4], bf[4][4];
                ldsm4(ah[0], abuf + s * 32);
                ldsm4(ah[1], abuf + 16 * ASTR * 2 + s * 32);
                #pragma unroll
                for (int gg = 0; gg < 4; gg++) ldsm4(bf[gg], b_addr[gg] + boff + s * 32);

                #pragma unroll
                for (int gg = 0; gg < 4; gg++) {
                    mma16816(acc[0][2 * gg],     ah[0], &bf[gg][0]);
                    mma16816(acc[0][2 * gg + 1], ah[0], &bf[gg][2]);
                    mma16816(acc[1][2 * gg],     ah[1], &bf[gg][0]);
                    mma16816(acc[1][2 * gg + 1], ah[1], &bf[gg][2]);
                }
            }
            __syncthreads();
        }

        // ---- epilogue ----
        #pragma unroll
        for (int ii = 0; ii < 2; ii++) {
            #pragma unroll
            for (int h = 0; h < 2; h++) {
                const int gm = m0 + wm * 32 + ii * 16 + grp + h * 8;
                if (gm >= MTOT) continue;
                if (MODE == 0) {
                    __half* pp = g_proj + (size_t)gm * 512 + nb * 256 + colw;
                    #pragma unroll
                    for (int j = 0; j < 8; j++) {
                        __half2 v = __floats2half2_rn(acc[ii][j][2 * h], acc[ii][j][2 * h + 1]);
                        *(__half2*)(pp + j * 8 + qc) = v;
                    }
                } else {
                    const int si = src[gm], ti2 = tgt[gm];
                    const __half* ps = g_proj + (size_t)si * 512 + colw;
                    const __half* pt = g_proj + (size_t)ti2 * 512 + 256 + colw;
                    const float* bb = bias + colw;
                    float* op = out + (size_t)gm * DD + colw;
                    #pragma unroll
                    for (int j = 0; j < 8; j++) {
                        const int cc = j * 8 + qc;
                        float2 sv = __half22float2(*(const __half2*)(ps + cc));
                        float2 tv = __half22float2(*(const __half2*)(pt + cc));
                        float2 bv = *(const float2*)(bb + cc);
                        float x = fmaf(acc[ii][j][2 * h]     + sv.x + tv.x, INV_SCALE, bv.x);
                        float y = fmaf(acc[ii][j][2 * h + 1] + sv.y + tv.y, INV_SCALE, bv.y);
                        *(float2*)(op + cc) = make_float2(fmaxf(x, 0.f), fmaxf(y, 0.f));
                    }
                }
            }
        }
    }
}

// ---------------------------------------------------------------------------
extern "C" void kernel_launch(void* const* d_in, const int* in_sizes, int n_in,
                              void* d_out, int out_size)
{
    const float* edge_feat = (const float*)d_in[0];
    const float* node_feat = (const float*)d_in[1];
    const int*   src_idx   = (const int*)d_in[2];
    const int*   tgt_idx   = (const int*)d_in[3];
    const float* W         = (const float*)d_in[4];
    const float* b         = (const float*)d_in[5];
    float* out = (float*)d_out;
    (void)in_sizes; (void)n_in; (void)out_size;

    cudaFuncSetAttribute(gemm_kernel<0>, cudaFuncAttributeMaxDynamicSharedMemorySize, SMEM_BYTES);
    cudaFuncSetAttribute(gemm_kernel<1>, cudaFuncAttributeMaxDynamicSharedMemorySize, SMEM_BYTES);

    prep_w<<<768, 256>>>(W);
    gemm_kernel<0><<<GRID, NTHR, SMEM_BYTES>>>(node_feat, nullptr, nullptr, nullptr, nullptr);
    gemm_kernel<1><<<GRID, NTHR, SMEM_BYTES>>>(edge_feat, src_idx, tgt_idx, b, out);
}